// round 1
// baseline (speedup 1.0000x reference)
#include <cuda_runtime.h>
#include <math.h>

#define NPTS 4096
#define NB   2
#define NN   (NPTS*NB)      // 8192 nodes
#define DIM  64
#define KNN  5
#define NKM  (NPTS*KNN)     // 20480 flat edges per batch
#define NEDGE (NKM*NB)      // 40960 edges total

// -------- scratch (static device globals; no runtime allocation) ----------
__device__ float g_X1 [NN*DIM];
__device__ float g_GE1[NN*DIM];
__device__ float g_GE2[NN*DIM];
__device__ float g_SQ [NN];
__device__ float g_D  [(size_t)NB*NPTS*NPTS];   // 128 MB distance scratch
__device__ int   g_NBR[NN*KNN];
__device__ float g_A  [NN*DIM];
__device__ float g_B  [NN*DIM];
__device__ float g_ACC1[NN*DIM];   // conv1 output
__device__ float g_ACC2[NN*DIM];   // conv2 output

// ---------------- pre_fc + embed1 + sq ----------------
__global__ void k_prefc(const float* __restrict__ x,
                        const float* __restrict__ Wp, const float* __restrict__ bp,
                        const float* __restrict__ Wd, const float* __restrict__ bd) {
    int v = blockIdx.x;            // node
    int o = threadIdx.x;           // 64 threads
    __shared__ float xr[32];
    __shared__ float x1r[64];
    __shared__ float red[64];
    if (o < 32) xr[o] = x[v*32 + o];
    __syncthreads();
    float acc = bp[o];
#pragma unroll
    for (int d = 0; d < 32; d++) acc = fmaf(xr[d], Wp[d*64 + o], acc);
    acc = acc > 0.f ? acc : 0.1f * acc;          // LeakyReLU(0.1)
    g_X1[v*64 + o] = acc;
    x1r[o] = acc;
    __syncthreads();
    float ge = bd[o];
#pragma unroll
    for (int d = 0; d < 64; d++) ge = fmaf(x1r[d], Wd[d*64 + o], ge);
    g_GE1[v*64 + o] = ge;
    red[o] = ge * ge;
    __syncthreads();
    for (int s = 32; s > 0; s >>= 1) { if (o < s) red[o] += red[o + s]; __syncthreads(); }
    if (o == 0) g_SQ[v] = red[0];
}

// ---------------- embed2 (concat(GE1, X2) @ W_d2) + sq ----------------
__global__ void k_embed2(const float* __restrict__ Wd, const float* __restrict__ bd) {
    int v = blockIdx.x, o = threadIdx.x;   // 64 threads
    __shared__ float gr[128];
    __shared__ float red[64];
    gr[o]      = g_GE1 [v*64 + o];
    gr[64 + o] = g_ACC1[v*64 + o];
    __syncthreads();
    float ge = bd[o];
#pragma unroll
    for (int d = 0; d < 128; d++) ge = fmaf(gr[d], Wd[d*64 + o], ge);
    g_GE2[v*64 + o] = ge;
    red[o] = ge * ge;
    __syncthreads();
    for (int s = 32; s > 0; s >>= 1) { if (o < s) red[o] += red[o + s]; __syncthreads(); }
    if (o == 0) g_SQ[v] = red[0];
}

// ---------------- pairwise distance GEMM: D[j][i] = max(sq_j+sq_i-2*dot,0)*t ----
__global__ void __launch_bounds__(256)
k_dist(int layer, const float* __restrict__ tptr) {
    const float* GE = layer ? g_GE2 : g_GE1;
    int bb = blockIdx.z;
    const float* G  = GE + bb*NPTS*DIM;
    const float* sq = g_SQ + bb*NPTS;
    float* Db = g_D + ((size_t)bb << 24);
    __shared__ float As[64][65];
    __shared__ float Bs[64][65];
    int tid = threadIdx.x;
    int jt = blockIdx.y << 6, it = blockIdx.x << 6;
#pragma unroll
    for (int r = 0; r < 16; r++) {
        int lin = (r << 8) + tid;
        int row = lin >> 6, col = lin & 63;
        As[row][col] = G[(jt + row)*64 + col];
        Bs[row][col] = G[(it + row)*64 + col];
    }
    __syncthreads();
    int ty = tid >> 4, tx = tid & 15;
    float acc[4][4];
#pragma unroll
    for (int u = 0; u < 4; u++)
#pragma unroll
        for (int v = 0; v < 4; v++) acc[u][v] = 0.f;
#pragma unroll
    for (int k = 0; k < 64; k++) {
        float a[4], b[4];
#pragma unroll
        for (int u = 0; u < 4; u++) { a[u] = As[(ty<<2)+u][k]; b[u] = Bs[(tx<<2)+u][k]; }
#pragma unroll
        for (int u = 0; u < 4; u++)
#pragma unroll
            for (int v = 0; v < 4; v++) acc[u][v] = fmaf(a[u], b[v], acc[u][v]);
    }
    float tv = tptr[0]; tv = fminf(fmaxf(tv, -5.f), 5.f);
    float t = expf(tv);
#pragma unroll
    for (int u = 0; u < 4; u++) {
        int j = jt + (ty << 2) + u;
        float sj = sq[j];
#pragma unroll
        for (int v = 0; v < 4; v++) {
            int i = it + (tx << 2) + v;
            Db[(size_t)j * NPTS + i] = fmaxf(sj + sq[i] - 2.f * acc[u][v], 0.f) * t;
        }
    }
}

// ---------------- top-5 smallest per row (= per column, symmetric) -----------
__global__ void k_topk() {
    int gw   = (blockIdx.x * blockDim.x + threadIdx.x) >> 5;   // global warp = bb*4096+j
    int lane = threadIdx.x & 31;
    if (gw >= NN) return;
    int bb = gw >> 12, j = gw & 4095;
    const float* row = g_D + ((size_t)bb << 24) + (size_t)j * NPTS;
    unsigned long long best[KNN];
#pragma unroll
    for (int u = 0; u < KNN; u++) best[u] = ~0ULL;
    for (int it = 0; it < NPTS/32; it++) {
        int i = lane + (it << 5);
        float d = row[i];
        unsigned long long key =
            ((unsigned long long)__float_as_uint(d) << 32) | (unsigned)i;
        if (key < best[KNN-1]) {
            best[KNN-1] = key;
#pragma unroll
            for (int u = KNN-1; u > 0; u--)
                if (best[u] < best[u-1]) {
                    unsigned long long tmp = best[u]; best[u] = best[u-1]; best[u-1] = tmp;
                }
        }
    }
    int ptr = 0;
#pragma unroll
    for (int r = 0; r < KNN; r++) {
        unsigned long long cand = (ptr < KNN) ? best[ptr] : ~0ULL;
        unsigned long long m = cand;
#pragma unroll
        for (int off = 16; off; off >>= 1) {
            unsigned long long o = __shfl_xor_sync(0xffffffffu, m, off);
            if (o < m) m = o;
        }
        if (cand == m && ptr < KNN) ptr++;   // keys unique (contain idx)
        if (lane == 0) g_NBR[gw * KNN + r] = (int)(m & 0xffffffffu);
    }
}

// ---------------- logprobs (faithful scrambled layout) ----------------
__global__ void k_logprobs(int layer, const float* __restrict__ tptr,
                           float* __restrict__ lp_out) {
    int gw   = (blockIdx.x * blockDim.x + threadIdx.x) >> 5;
    int lane = threadIdx.x & 31;
    if (gw >= NB * NKM) return;
    int bb = gw / NKM, m = gw % NKM;
    int k = m >> 12, jj = m & 4095;          // flat is k-major
    int a = g_NBR[(bb*NPTS + jj)*KNN + k];
    int p = m / KNN, q = m % KNN;            // logprob slot is node-major
    const float* GE = layer ? g_GE2 : g_GE1;
    const float* ga = GE + (bb*NPTS + a)*DIM;
    const float* gp = GE + (bb*NPTS + p)*DIM;
    float s = 0.f;
#pragma unroll
    for (int u = 0; u < 2; u++) {
        float d = ga[lane + 32*u] - gp[lane + 32*u];
        s = fmaf(d, d, s);
    }
#pragma unroll
    for (int off = 16; off; off >>= 1) s += __shfl_xor_sync(0xffffffffu, s, off);
    if (lane == 0) {
        float tv = tptr[0]; tv = fminf(fmaxf(tv, -5.f), 5.f);
        float t = expf(tv);
        lp_out[((bb*NPTS + p)*KNN + q)*2 + layer] = -s * t;
    }
}

// ---------------- EdgeConv node pre-GEMMs: A=X@(Wtop-Wbot), B=X@Wbot, ACC=0 ---
__global__ void k_AB(int layer, const float* __restrict__ W) {
    int v = blockIdx.x, o = threadIdx.x;   // 64 threads
    const float* X = layer ? g_ACC1 : g_X1;
    float* ACC = layer ? g_ACC2 : g_ACC1;
    __shared__ float xr[64];
    xr[o] = X[v*64 + o];
    __syncthreads();
    float a = 0.f, b = 0.f;
#pragma unroll
    for (int d = 0; d < 64; d++) {
        float w1 = W[d*64 + o], w2 = W[(64 + d)*64 + o];
        float xd = xr[d];
        a = fmaf(xd, w1 - w2, a);
        b = fmaf(xd, w2, b);
    }
    g_A[v*64 + o] = a;
    g_B[v*64 + o] = b;
    ACC[v*64 + o] = 0.f;                   // init: relu(empty-seg)=0, relu(max)=max(.,0)
}

// ---------------- EdgeConv scatter-max ----------------
__global__ void k_scatter(int layer, const float* __restrict__ bias) {
    int tid = blockIdx.x * blockDim.x + threadIdx.x;   // (edge, half)
    if (tid >= NEDGE * 2) return;
    int s  = tid >> 1, h = tid & 1;
    int p0 = s >> 2, bb = (s >> 1) & 1, c = s & 1;
    // src = e[0][s] : flat[bb,p0] | p0//K    (k-major flat, node-major centers)
    int src, dst;
    if (c == 0) src = g_NBR[(bb*NPTS + (p0 & 4095))*KNN + (p0 >> 12)] + bb*NPTS;
    else        src = p0 / KNN + bb*NPTS;
    int p1 = p0 + NKM/2;                   // +10240: second linear half
    if (c == 0) dst = g_NBR[(bb*NPTS + (p1 & 4095))*KNN + (p1 >> 12)] + bb*NPTS;
    else        dst = p1 / KNN + bb*NPTS;

    float* ACC = layer ? g_ACC2 : g_ACC1;
    const float4* Ad = (const float4*)(g_A + dst*64 + h*32);
    const float4* Bv = (const float4*)(g_B + src*64 + h*32);
    const float4* Bi = (const float4*)(bias + h*32);
    int* out = (int*)(ACC + dst*64 + h*32);
#pragma unroll
    for (int o = 0; o < 8; o++) {
        float4 av = Ad[o], bv = Bv[o], bi = Bi[o];
        float m0 = av.x + bv.x + bi.x;
        float m1 = av.y + bv.y + bi.y;
        float m2 = av.z + bv.z + bi.z;
        float m3 = av.w + bv.w + bi.w;
        // ACC>=0 invariant: only positive messages can win against relu floor 0
        if (m0 > 0.f) atomicMax(&out[o*4 + 0], __float_as_int(m0));
        if (m1 > 0.f) atomicMax(&out[o*4 + 1], __float_as_int(m1));
        if (m2 > 0.f) atomicMax(&out[o*4 + 2], __float_as_int(m2));
        if (m3 > 0.f) atomicMax(&out[o*4 + 3], __float_as_int(m3));
    }
}

// ---------------- final MLP 64 -> 32 -> 8 ----------------
__global__ void k_fc(const float* __restrict__ W1, const float* __restrict__ b1,
                     const float* __restrict__ W2, const float* __restrict__ b2,
                     float* __restrict__ out) {
    int v = blockIdx.x, o = threadIdx.x;   // 32 threads
    __shared__ float xr[64];
    __shared__ float hr[32];
    xr[o]      = g_ACC2[v*64 + o];
    xr[32 + o] = g_ACC2[v*64 + 32 + o];
    __syncthreads();
    float hh = b1[o];
#pragma unroll
    for (int d = 0; d < 64; d++) hh = fmaf(xr[d], W1[d*32 + o], hh);
    hh = hh > 0.f ? hh : 0.1f * hh;
    hr[o] = hh;
    __syncthreads();
    if (o < 8) {
        float acc = b2[o];
#pragma unroll
        for (int d = 0; d < 32; d++) acc = fmaf(hr[d], W2[d*8 + o], acc);
        out[v*8 + o] = acc;
    }
}

// ======================= launcher =======================
extern "C" void kernel_launch(void* const* d_in, const int* in_sizes, int n_in,
                              void* d_out, int out_size) {
    const float* x     = (const float*)d_in[0];
    const float* W_pre = (const float*)d_in[1];
    const float* b_pre = (const float*)d_in[2];
    const float* W_d1  = (const float*)d_in[3];
    const float* b_d1  = (const float*)d_in[4];
    const float* t1    = (const float*)d_in[5];
    const float* W_c1  = (const float*)d_in[6];
    const float* b_c1  = (const float*)d_in[7];
    const float* W_d2  = (const float*)d_in[8];
    const float* b_d2  = (const float*)d_in[9];
    const float* t2    = (const float*)d_in[10];
    const float* W_c2  = (const float*)d_in[11];
    const float* b_c2  = (const float*)d_in[12];
    const float* W_f1  = (const float*)d_in[13];
    const float* b_f1  = (const float*)d_in[14];
    const float* W_f2  = (const float*)d_in[15];
    const float* b_f2  = (const float*)d_in[16];

    float* out = (float*)d_out;                 // [2,4096,8]
    float* lp  = out + NN * 8;                  // [2,4096,5,2]

    // layer 0 graph
    k_prefc<<<NN, 64>>>(x, W_pre, b_pre, W_d1, b_d1);
    k_dist<<<dim3(NPTS/64, NPTS/64, NB), 256>>>(0, t1);
    k_topk<<<(NN*32 + 255)/256, 256>>>();
    k_logprobs<<<(NB*NKM*32 + 255)/256, 256>>>(0, t1, lp);
    k_AB<<<NN, 64>>>(0, W_c1);
    k_scatter<<<(NEDGE*2 + 255)/256, 256>>>(0, b_c1);

    // layer 1 graph
    k_embed2<<<NN, 64>>>(W_d2, b_d2);
    k_dist<<<dim3(NPTS/64, NPTS/64, NB), 256>>>(1, t2);
    k_topk<<<(NN*32 + 255)/256, 256>>>();
    k_logprobs<<<(NB*NKM*32 + 255)/256, 256>>>(1, t2, lp);
    k_AB<<<NN, 64>>>(1, W_c2);
    k_scatter<<<(NEDGE*2 + 255)/256, 256>>>(1, b_c2);

    // head
    k_fc<<<NN, 32>>>(W_f1, b_f1, W_f2, b_f2, out);
}

// round 2
// speedup vs baseline: 1.3578x; 1.3578x over previous
#include <cuda_runtime.h>
#include <math.h>

#define NPTS 4096
#define NB   2
#define NN   (NPTS*NB)      // 8192 nodes
#define DIM  64
#define KNN  5
#define NKM  (NPTS*KNN)     // 20480 flat edges per batch
#define NEDGE (NKM*NB)      // 40960 edges total
#define NT   32             // 4096/128 tiles per side
#define NITEMS_B (NT*(NT+1)/2)   // 528 upper-tri items per batch
#define NITEMS   (NB*NITEMS_B)   // 1056

#define SMEM_BYTES ((64*128*2 + 128*129)*4 + 2*128*2*KNN*8)  // 152064

// -------- scratch (static device globals; no runtime allocation) ----------
__device__ float g_X1 [NN*DIM];
__device__ float g_GE1[NN*DIM];
__device__ float g_GE2[NN*DIM];
__device__ float g_SQ [NN];
__device__ unsigned long long g_CAND[(size_t)NN*NT*KNN];   // 10.5 MB candidates
__device__ int   g_NBR[NN*KNN];
__device__ float g_A  [NN*DIM];
__device__ float g_B  [NN*DIM];
__device__ float g_ACC1[NN*DIM];
__device__ float g_ACC2[NN*DIM];

__device__ __forceinline__ int swz4(int c)  { return c ^ (c >> 3); }              // float4-chunk swizzle in 128-float row
__device__ __forceinline__ int dswz(int c)  { return c ^ (((c >> 5) & 3) << 1); } // Ds scalar column swizzle

// ---------------- pre_fc + embed1 + sq ----------------
__global__ void k_prefc(const float* __restrict__ x,
                        const float* __restrict__ Wp, const float* __restrict__ bp,
                        const float* __restrict__ Wd, const float* __restrict__ bd) {
    int v = blockIdx.x;
    int o = threadIdx.x;           // 64 threads
    __shared__ float xr[32];
    __shared__ float x1r[64];
    __shared__ float red[64];
    if (o < 32) xr[o] = x[v*32 + o];
    __syncthreads();
    float acc = bp[o];
#pragma unroll
    for (int d = 0; d < 32; d++) acc = fmaf(xr[d], Wp[d*64 + o], acc);
    acc = acc > 0.f ? acc : 0.1f * acc;          // LeakyReLU(0.1)
    g_X1[v*64 + o] = acc;
    x1r[o] = acc;
    __syncthreads();
    float ge = bd[o];
#pragma unroll
    for (int d = 0; d < 64; d++) ge = fmaf(x1r[d], Wd[d*64 + o], ge);
    g_GE1[v*64 + o] = ge;
    red[o] = ge * ge;
    __syncthreads();
    for (int s = 32; s > 0; s >>= 1) { if (o < s) red[o] += red[o + s]; __syncthreads(); }
    if (o == 0) g_SQ[v] = red[0];
}

// ---------------- embed2 (concat(GE1, X2) @ W_d2) + sq ----------------
__global__ void k_embed2(const float* __restrict__ Wd, const float* __restrict__ bd) {
    int v = blockIdx.x, o = threadIdx.x;   // 64 threads
    __shared__ float gr[128];
    __shared__ float red[64];
    gr[o]      = g_GE1 [v*64 + o];
    gr[64 + o] = g_ACC1[v*64 + o];
    __syncthreads();
    float ge = bd[o];
#pragma unroll
    for (int d = 0; d < 128; d++) ge = fmaf(gr[d], Wd[d*64 + o], ge);
    g_GE2[v*64 + o] = ge;
    red[o] = ge * ge;
    __syncthreads();
    for (int s = 32; s > 0; s >>= 1) { if (o < s) red[o] += red[o + s]; __syncthreads(); }
    if (o == 0) g_SQ[v] = red[0];
}

// ============ fused symmetric distance GEMM + per-tile top-5 extraction ============
// One block = one upper-triangle tile pair (rt, ct), rt <= ct, of 128x128 distances.
// Emits top-5 candidates (key = dist_bits<<32 | col_idx) for rows (slot ct) and,
// if off-diagonal, for cols (slot rt).
__global__ void __launch_bounds__(256)
k_fused(int layer) {
    extern __shared__ float sm[];
    float* As = sm;                        // [64 k][128 rows] swizzled
    float* Bs = sm + 64*128;
    float* Ds = sm + 2*64*128;             // [128][129] swizzled cols
    unsigned long long* Sc_r = (unsigned long long*)(sm + 2*64*128 + 128*129);
    unsigned long long* Sc_c = Sc_r + 128*2*KNN;

    const float* GE = layer ? g_GE2 : g_GE1;
    int item = blockIdx.x;
    int bb  = item / NITEMS_B;
    int tri = item - bb*NITEMS_B;
    int rt = 0;
    while (tri >= NT - rt) { tri -= NT - rt; rt++; }
    int ct = rt + tri;

    const float* G  = GE + bb*NPTS*DIM;
    const float* sq = g_SQ + bb*NPTS;
    int tid = threadIdx.x;

    // --- load both 128x64 tiles, transposed to k-major with chunk swizzle ---
    const float4* G4 = (const float4*)G;
    int i16 = tid & 15;           // row low bits
    int kq  = tid >> 4;           // k-quad 0..15
#pragma unroll
    for (int it = 0; it < 8; it++) {
        int row = it*16 + i16;
        float4 va = G4[(rt*128 + row)*16 + kq];
        float4 vb = G4[(ct*128 + row)*16 + kq];
        int base = swz4(row >> 2)*4 + (row & 3);
        As[(kq*4+0)*128 + base] = va.x;
        As[(kq*4+1)*128 + base] = va.y;
        As[(kq*4+2)*128 + base] = va.z;
        As[(kq*4+3)*128 + base] = va.w;
        Bs[(kq*4+0)*128 + base] = vb.x;
        Bs[(kq*4+1)*128 + base] = vb.y;
        Bs[(kq*4+2)*128 + base] = vb.z;
        Bs[(kq*4+3)*128 + base] = vb.w;
    }
    __syncthreads();

    // --- 128x128x64 GEMM, 8x8 per thread ---
    int ty = tid >> 4, tx = tid & 15;
    const float4* As4 = (const float4*)As;
    const float4* Bs4 = (const float4*)Bs;
    int pa0 = swz4(2*ty), pa1 = swz4(2*ty+1);
    int pb0 = swz4(2*tx), pb1 = swz4(2*tx+1);
    float acc[8][8];
#pragma unroll
    for (int u = 0; u < 8; u++)
#pragma unroll
        for (int v = 0; v < 8; v++) acc[u][v] = 0.f;

#pragma unroll 8
    for (int k = 0; k < 64; k++) {
        float4 a0 = As4[k*32 + pa0];
        float4 a1 = As4[k*32 + pa1];
        float4 b0 = Bs4[k*32 + pb0];
        float4 b1 = Bs4[k*32 + pb1];
        float a[8] = {a0.x,a0.y,a0.z,a0.w,a1.x,a1.y,a1.z,a1.w};
        float b[8] = {b0.x,b0.y,b0.z,b0.w,b1.x,b1.y,b1.z,b1.w};
#pragma unroll
        for (int u = 0; u < 8; u++)
#pragma unroll
            for (int v = 0; v < 8; v++)
                acc[u][v] = fmaf(a[u], b[v], acc[u][v]);
    }

    // --- distances to smem (t>0 is monotone; omit it for selection) ---
    float sqr[8], sqc[8];
#pragma unroll
    for (int u = 0; u < 8; u++) sqr[u] = sq[rt*128 + ty*8 + u];
#pragma unroll
    for (int v = 0; v < 8; v++) sqc[v] = sq[ct*128 + tx*8 + v];
#pragma unroll
    for (int u = 0; u < 8; u++) {
        int r = ty*8 + u;
#pragma unroll
        for (int v = 0; v < 8; v++) {
            int c = tx*8 + v;
            Ds[r*129 + dswz(c)] = fmaxf(sqr[u] + sqc[v] - 2.f*acc[u][v], 0.f);
        }
    }
    __syncthreads();

    // --- row scan: top-5 per row over this tile's 128 cols (2 threads/row) ---
    {
        int r = tid >> 1, h = tid & 1;
        unsigned long long best[KNN];
#pragma unroll
        for (int j = 0; j < KNN; j++) best[j] = ~0ULL;
        for (int c = 0; c < 64; c++) {
            int col = h*64 + c;
            float d = Ds[r*129 + dswz(col)];
            unsigned long long key =
                ((unsigned long long)__float_as_uint(d) << 32) | (unsigned)(ct*128 + col);
            if (key < best[KNN-1]) {
                best[KNN-1] = key;
#pragma unroll
                for (int j = KNN-1; j > 0; j--)
                    if (best[j] < best[j-1]) {
                        unsigned long long t2 = best[j]; best[j] = best[j-1]; best[j-1] = t2;
                    }
            }
        }
#pragma unroll
        for (int j = 0; j < KNN; j++) Sc_r[(r*2+h)*KNN + j] = best[j];
    }
    // --- col scan (transposed candidates) for off-diagonal tiles ---
    if (rt != ct) {
        int c = tid >> 1, h = tid & 1;
        unsigned long long best[KNN];
#pragma unroll
        for (int j = 0; j < KNN; j++) best[j] = ~0ULL;
        for (int rr = 0; rr < 64; rr++) {
            int row = h*64 + rr;
            float d = Ds[row*129 + dswz(c)];
            unsigned long long key =
                ((unsigned long long)__float_as_uint(d) << 32) | (unsigned)(rt*128 + row);
            if (key < best[KNN-1]) {
                best[KNN-1] = key;
#pragma unroll
                for (int j = KNN-1; j > 0; j--)
                    if (best[j] < best[j-1]) {
                        unsigned long long t2 = best[j]; best[j] = best[j-1]; best[j-1] = t2;
                    }
            }
        }
#pragma unroll
        for (int j = 0; j < KNN; j++) Sc_c[(c*2+h)*KNN + j] = best[j];
    }
    __syncthreads();

    // --- merge the two halves per row/col, write candidate slots ---
    if (tid < 128) {
        const unsigned long long* xk = &Sc_r[(tid*2+0)*KNN];
        const unsigned long long* yk = &Sc_r[(tid*2+1)*KNN];
        unsigned long long out[KNN];
        int i = 0, j = 0;
#pragma unroll
        for (int r2 = 0; r2 < KNN; r2++) {
            unsigned long long xv = xk[i], yv = yk[j];
            if (xv <= yv) { out[r2] = xv; i++; } else { out[r2] = yv; j++; }
        }
        size_t rowg = (size_t)(bb*NPTS + rt*128 + tid);
#pragma unroll
        for (int j2 = 0; j2 < KNN; j2++) g_CAND[(rowg*NT + ct)*KNN + j2] = out[j2];
    } else if (rt != ct) {
        int c = tid - 128;
        const unsigned long long* xk = &Sc_c[(c*2+0)*KNN];
        const unsigned long long* yk = &Sc_c[(c*2+1)*KNN];
        unsigned long long out[KNN];
        int i = 0, j = 0;
#pragma unroll
        for (int r2 = 0; r2 < KNN; r2++) {
            unsigned long long xv = xk[i], yv = yk[j];
            if (xv <= yv) { out[r2] = xv; i++; } else { out[r2] = yv; j++; }
        }
        size_t rowg = (size_t)(bb*NPTS + ct*128 + c);
#pragma unroll
        for (int j2 = 0; j2 < KNN; j2++) g_CAND[(rowg*NT + rt)*KNN + j2] = out[j2];
    }
}

// ---------------- merge 32 sorted 5-lists per row -> global top-5 ----------------
__global__ void k_merge() {
    int gw   = (blockIdx.x * blockDim.x + threadIdx.x) >> 5;   // row
    int lane = threadIdx.x & 31;
    if (gw >= NN) return;
    const unsigned long long* cp = g_CAND + ((size_t)gw*NT + lane)*KNN;
    unsigned long long keys[KNN];
#pragma unroll
    for (int j = 0; j < KNN; j++) keys[j] = cp[j];
#pragma unroll
    for (int r = 0; r < KNN; r++) {
        unsigned long long cand = keys[0];
        unsigned long long m = cand;
#pragma unroll
        for (int off = 16; off; off >>= 1) {
            unsigned long long o = __shfl_xor_sync(0xffffffffu, m, off);
            if (o < m) m = o;
        }
        if (m == cand) {   // keys unique (contain index): exactly one winner
#pragma unroll
            for (int j = 0; j < KNN-1; j++) keys[j] = keys[j+1];
            keys[KNN-1] = ~0ULL;
        }
        if (lane == 0) g_NBR[gw*KNN + r] = (int)(m & 0xffffffffu);
    }
}

// ---------------- logprobs (faithful scrambled layout) ----------------
__global__ void k_logprobs(int layer, const float* __restrict__ tptr,
                           float* __restrict__ lp_out) {
    int gw   = (blockIdx.x * blockDim.x + threadIdx.x) >> 5;
    int lane = threadIdx.x & 31;
    if (gw >= NB * NKM) return;
    int bb = gw / NKM, m = gw % NKM;
    int k = m >> 12, jj = m & 4095;          // flat is k-major
    int a = g_NBR[(bb*NPTS + jj)*KNN + k];
    int p = m / KNN, q = m % KNN;            // logprob slot is node-major
    const float* GE = layer ? g_GE2 : g_GE1;
    const float* ga = GE + (bb*NPTS + a)*DIM;
    const float* gp = GE + (bb*NPTS + p)*DIM;
    float s = 0.f;
#pragma unroll
    for (int u = 0; u < 2; u++) {
        float d = ga[lane + 32*u] - gp[lane + 32*u];
        s = fmaf(d, d, s);
    }
#pragma unroll
    for (int off = 16; off; off >>= 1) s += __shfl_xor_sync(0xffffffffu, s, off);
    if (lane == 0) {
        float tv = tptr[0]; tv = fminf(fmaxf(tv, -5.f), 5.f);
        float t = expf(tv);
        lp_out[((bb*NPTS + p)*KNN + q)*2 + layer] = -s * t;
    }
}

// ---------------- EdgeConv node pre-GEMMs: A=X@(Wtop-Wbot), B=X@Wbot, ACC=0 ---
__global__ void k_AB(int layer, const float* __restrict__ W) {
    int v = blockIdx.x, o = threadIdx.x;   // 64 threads
    const float* X = layer ? g_ACC1 : g_X1;
    float* ACC = layer ? g_ACC2 : g_ACC1;
    __shared__ float xr[64];
    xr[o] = X[v*64 + o];
    __syncthreads();
    float a = 0.f, b = 0.f;
#pragma unroll
    for (int d = 0; d < 64; d++) {
        float w1 = W[d*64 + o], w2 = W[(64 + d)*64 + o];
        float xd = xr[d];
        a = fmaf(xd, w1 - w2, a);
        b = fmaf(xd, w2, b);
    }
    g_A[v*64 + o] = a;
    g_B[v*64 + o] = b;
    ACC[v*64 + o] = 0.f;
}

// ---------------- EdgeConv scatter-max ----------------
__global__ void k_scatter(int layer, const float* __restrict__ bias) {
    int tid = blockIdx.x * blockDim.x + threadIdx.x;   // (edge, half)
    if (tid >= NEDGE * 2) return;
    int s  = tid >> 1, h = tid & 1;
    int p0 = s >> 2, bb = (s >> 1) & 1, c = s & 1;
    int src, dst;
    if (c == 0) src = g_NBR[(bb*NPTS + (p0 & 4095))*KNN + (p0 >> 12)] + bb*NPTS;
    else        src = p0 / KNN + bb*NPTS;
    int p1 = p0 + NKM/2;
    if (c == 0) dst = g_NBR[(bb*NPTS + (p1 & 4095))*KNN + (p1 >> 12)] + bb*NPTS;
    else        dst = p1 / KNN + bb*NPTS;

    float* ACC = layer ? g_ACC2 : g_ACC1;
    const float4* Ad = (const float4*)(g_A + dst*64 + h*32);
    const float4* Bv = (const float4*)(g_B + src*64 + h*32);
    const float4* Bi = (const float4*)(bias + h*32);
    int* out = (int*)(ACC + dst*64 + h*32);
#pragma unroll
    for (int o = 0; o < 8; o++) {
        float4 av = Ad[o], bv = Bv[o], bi = Bi[o];
        float m0 = av.x + bv.x + bi.x;
        float m1 = av.y + bv.y + bi.y;
        float m2 = av.z + bv.z + bi.z;
        float m3 = av.w + bv.w + bi.w;
        if (m0 > 0.f) atomicMax(&out[o*4 + 0], __float_as_int(m0));
        if (m1 > 0.f) atomicMax(&out[o*4 + 1], __float_as_int(m1));
        if (m2 > 0.f) atomicMax(&out[o*4 + 2], __float_as_int(m2));
        if (m3 > 0.f) atomicMax(&out[o*4 + 3], __float_as_int(m3));
    }
}

// ---------------- final MLP 64 -> 32 -> 8 ----------------
__global__ void k_fc(const float* __restrict__ W1, const float* __restrict__ b1,
                     const float* __restrict__ W2, const float* __restrict__ b2,
                     float* __restrict__ out) {
    int v = blockIdx.x, o = threadIdx.x;   // 32 threads
    __shared__ float xr[64];
    __shared__ float hr[32];
    xr[o]      = g_ACC2[v*64 + o];
    xr[32 + o] = g_ACC2[v*64 + 32 + o];
    __syncthreads();
    float hh = b1[o];
#pragma unroll
    for (int d = 0; d < 64; d++) hh = fmaf(xr[d], W1[d*32 + o], hh);
    hh = hh > 0.f ? hh : 0.1f * hh;
    hr[o] = hh;
    __syncthreads();
    if (o < 8) {
        float acc = b2[o];
#pragma unroll
        for (int d = 0; d < 32; d++) acc = fmaf(hr[d], W2[d*8 + o], acc);
        out[v*8 + o] = acc;
    }
}

// ======================= launcher =======================
extern "C" void kernel_launch(void* const* d_in, const int* in_sizes, int n_in,
                              void* d_out, int out_size) {
    const float* x     = (const float*)d_in[0];
    const float* W_pre = (const float*)d_in[1];
    const float* b_pre = (const float*)d_in[2];
    const float* W_d1  = (const float*)d_in[3];
    const float* b_d1  = (const float*)d_in[4];
    const float* t1    = (const float*)d_in[5];
    const float* W_c1  = (const float*)d_in[6];
    const float* b_c1  = (const float*)d_in[7];
    const float* W_d2  = (const float*)d_in[8];
    const float* b_d2  = (const float*)d_in[9];
    const float* t2    = (const float*)d_in[10];
    const float* W_c2  = (const float*)d_in[11];
    const float* b_c2  = (const float*)d_in[12];
    const float* W_f1  = (const float*)d_in[13];
    const float* b_f1  = (const float*)d_in[14];
    const float* W_f2  = (const float*)d_in[15];
    const float* b_f2  = (const float*)d_in[16];

    float* out = (float*)d_out;                 // [2,4096,8]
    float* lp  = out + NN * 8;                  // [2,4096,5,2]

    cudaFuncSetAttribute(k_fused, cudaFuncAttributeMaxDynamicSharedMemorySize, SMEM_BYTES);

    // layer 1
    k_prefc<<<NN, 64>>>(x, W_pre, b_pre, W_d1, b_d1);
    k_fused<<<NITEMS, 256, SMEM_BYTES>>>(0);
    k_merge<<<NN/8, 256>>>();
    k_logprobs<<<(NB*NKM*32 + 255)/256, 256>>>(0, t1, lp);
    k_AB<<<NN, 64>>>(0, W_c1);
    k_scatter<<<(NEDGE*2 + 255)/256, 256>>>(0, b_c1);

    // layer 2
    k_embed2<<<NN, 64>>>(W_d2, b_d2);
    k_fused<<<NITEMS, 256, SMEM_BYTES>>>(1);
    k_merge<<<NN/8, 256>>>();
    k_logprobs<<<(NB*NKM*32 + 255)/256, 256>>>(1, t2, lp);
    k_AB<<<NN, 64>>>(1, W_c2);
    k_scatter<<<(NEDGE*2 + 255)/256, 256>>>(1, b_c2);

    // head
    k_fc<<<NN, 32>>>(W_f1, b_f1, W_f2, b_f2, out);
}

// round 3
// speedup vs baseline: 1.6119x; 1.1871x over previous
#include <cuda_runtime.h>
#include <math.h>

#define NPTS 4096
#define NB   2
#define NN   (NPTS*NB)      // 8192 nodes
#define DIM  64
#define KNN  5
#define NKM  (NPTS*KNN)     // 20480 flat edges per batch
#define NEDGE (NKM*NB)      // 40960 edges total
#define NT   32             // 4096/128 tiles per side
#define NITEMS_B (NT*(NT+1)/2)   // 528 upper-tri items per batch
#define NITEMS   (NB*NITEMS_B)   // 1056

#define PADW 132
#define SMEMF ((32*128*2 + 128*PADW)*4)   // 100352 bytes -> 2 blocks/SM

// -------- scratch (static device globals; no runtime allocation) ----------
__device__ float g_X1 [NN*DIM];
__device__ float g_GE1[NN*DIM];
__device__ float g_GE2[NN*DIM];
__device__ float g_SQ [NN];
__device__ unsigned long long g_CAND[(size_t)NN*NT*KNN];   // 10.5 MB candidates
__device__ int   g_NBR[NN*KNN];
__device__ float g_A  [NN*DIM];
__device__ float g_B  [NN*DIM];
__device__ float g_ACC1[NN*DIM];
__device__ float g_ACC2[NN*DIM];

__device__ __forceinline__ int swz4(int c)  { return c ^ (c >> 3); }

// ---------------- pre_fc + embed1 + sq ----------------
__global__ void k_prefc(const float* __restrict__ x,
                        const float* __restrict__ Wp, const float* __restrict__ bp,
                        const float* __restrict__ Wd, const float* __restrict__ bd) {
    int v = blockIdx.x;
    int o = threadIdx.x;           // 64 threads
    __shared__ float xr[32];
    __shared__ float x1r[64];
    __shared__ float red[64];
    if (o < 32) xr[o] = x[v*32 + o];
    __syncthreads();
    float acc = bp[o];
#pragma unroll
    for (int d = 0; d < 32; d++) acc = fmaf(xr[d], Wp[d*64 + o], acc);
    acc = acc > 0.f ? acc : 0.1f * acc;          // LeakyReLU(0.1)
    g_X1[v*64 + o] = acc;
    x1r[o] = acc;
    __syncthreads();
    float ge = bd[o];
#pragma unroll
    for (int d = 0; d < 64; d++) ge = fmaf(x1r[d], Wd[d*64 + o], ge);
    g_GE1[v*64 + o] = ge;
    red[o] = ge * ge;
    __syncthreads();
    for (int s = 32; s > 0; s >>= 1) { if (o < s) red[o] += red[o + s]; __syncthreads(); }
    if (o == 0) g_SQ[v] = red[0];
}

// ---------------- embed2 (concat(GE1, X2) @ W_d2) + sq ----------------
__global__ void k_embed2(const float* __restrict__ Wd, const float* __restrict__ bd) {
    int v = blockIdx.x, o = threadIdx.x;   // 64 threads
    __shared__ float gr[128];
    __shared__ float red[64];
    gr[o]      = g_GE1 [v*64 + o];
    gr[64 + o] = g_ACC1[v*64 + o];
    __syncthreads();
    float ge = bd[o];
#pragma unroll
    for (int d = 0; d < 128; d++) ge = fmaf(gr[d], Wd[d*64 + o], ge);
    g_GE2[v*64 + o] = ge;
    red[o] = ge * ge;
    __syncthreads();
    for (int s = 32; s > 0; s >>= 1) { if (o < s) red[o] += red[o + s]; __syncthreads(); }
    if (o == 0) g_SQ[v] = red[0];
}

// ---- merge two sorted 5-lists held by adjacent lanes (xor 1); result in best ----
__device__ __forceinline__ void merge_pair(unsigned long long best[KNN]) {
    unsigned long long other[KNN];
#pragma unroll
    for (int j = 0; j < KNN; j++) other[j] = __shfl_xor_sync(0xffffffffu, best[j], 1);
#pragma unroll
    for (int j = 0; j < KNN; j++) {
        unsigned long long key = other[j];
        if (key < best[KNN-1]) {
            best[KNN-1] = key;
#pragma unroll
            for (int u = KNN-1; u > 0; u--)
                if (best[u] < best[u-1]) {
                    unsigned long long t2 = best[u]; best[u] = best[u-1]; best[u-1] = t2;
                }
        }
    }
}

// ============ fused symmetric distance GEMM + per-tile top-5 extraction ============
__global__ void __launch_bounds__(256, 2)
k_fused(int layer) {
    extern __shared__ float sm[];
    float* As = sm;                 // [32 k][128 rows] chunk-swizzled
    float* Bs = sm + 32*128;
    float* Ds = sm + 64*128;        // [128][PADW]

    const float* GE = layer ? g_GE2 : g_GE1;
    int item = blockIdx.x;
    int bb  = item / NITEMS_B;
    int tri = item - bb*NITEMS_B;
    int rt = 0;
    while (tri >= NT - rt) { tri -= NT - rt; rt++; }
    int ct = rt + tri;

    const float* G  = GE + bb*NPTS*DIM;
    const float* sq = g_SQ + bb*NPTS;
    int tid = threadIdx.x;
    int ty = tid >> 4, tx = tid & 15;
    int r32 = tid & 31;             // row subgroup for loading
    int kq2 = tid >> 5;             // 0..7: float4-of-k index within chunk
    const float4* G4 = (const float4*)G;
    const float4* As4 = (const float4*)As;
    const float4* Bs4 = (const float4*)Bs;
    int pa0 = swz4(2*ty), pa1 = swz4(2*ty+1);
    int pb0 = swz4(2*tx), pb1 = swz4(2*tx+1);

    float acc[8][8];
#pragma unroll
    for (int u = 0; u < 8; u++)
#pragma unroll
        for (int v = 0; v < 8; v++) acc[u][v] = 0.f;

#pragma unroll
    for (int chunk = 0; chunk < 2; chunk++) {
        if (chunk) __syncthreads();          // protect smem reuse
#pragma unroll
        for (int it = 0; it < 4; it++) {
            int row = it*32 + r32;
            float4 va = G4[(rt*128 + row)*16 + chunk*8 + kq2];
            float4 vb = G4[(ct*128 + row)*16 + chunk*8 + kq2];
            int base = swz4(row >> 2)*4 + (row & 3);
            As[(kq2*4+0)*128 + base] = va.x;
            As[(kq2*4+1)*128 + base] = va.y;
            As[(kq2*4+2)*128 + base] = va.z;
            As[(kq2*4+3)*128 + base] = va.w;
            Bs[(kq2*4+0)*128 + base] = vb.x;
            Bs[(kq2*4+1)*128 + base] = vb.y;
            Bs[(kq2*4+2)*128 + base] = vb.z;
            Bs[(kq2*4+3)*128 + base] = vb.w;
        }
        __syncthreads();
#pragma unroll 8
        for (int k = 0; k < 32; k++) {
            float4 a0 = As4[k*32 + pa0];
            float4 a1 = As4[k*32 + pa1];
            float4 b0 = Bs4[k*32 + pb0];
            float4 b1 = Bs4[k*32 + pb1];
            float a[8] = {a0.x,a0.y,a0.z,a0.w,a1.x,a1.y,a1.z,a1.w};
            float b[8] = {b0.x,b0.y,b0.z,b0.w,b1.x,b1.y,b1.z,b1.w};
#pragma unroll
            for (int u = 0; u < 8; u++)
#pragma unroll
                for (int v = 0; v < 8; v++)
                    acc[u][v] = fmaf(a[u], b[v], acc[u][v]);
        }
    }

    // --- distances to smem (selection is monotone in t; omit it) ---
    float sqr[8], sqc[8];
#pragma unroll
    for (int u = 0; u < 8; u++) sqr[u] = sq[rt*128 + ty*8 + u];
#pragma unroll
    for (int v = 0; v < 8; v++) sqc[v] = sq[ct*128 + tx*8 + v];
#pragma unroll
    for (int u = 0; u < 8; u++) {
        int r = ty*8 + u;
        float4 d0, d1;
        d0.x = fmaxf(sqr[u] + sqc[0] - 2.f*acc[u][0], 0.f);
        d0.y = fmaxf(sqr[u] + sqc[1] - 2.f*acc[u][1], 0.f);
        d0.z = fmaxf(sqr[u] + sqc[2] - 2.f*acc[u][2], 0.f);
        d0.w = fmaxf(sqr[u] + sqc[3] - 2.f*acc[u][3], 0.f);
        d1.x = fmaxf(sqr[u] + sqc[4] - 2.f*acc[u][4], 0.f);
        d1.y = fmaxf(sqr[u] + sqc[5] - 2.f*acc[u][5], 0.f);
        d1.z = fmaxf(sqr[u] + sqc[6] - 2.f*acc[u][6], 0.f);
        d1.w = fmaxf(sqr[u] + sqc[7] - 2.f*acc[u][7], 0.f);
        *(float4*)(Ds + r*PADW + tx*8)     = d0;
        *(float4*)(Ds + r*PADW + tx*8 + 4) = d1;
    }
    __syncthreads();

    // --- row scan: 2 threads/row, interleaved columns, shfl-pair merge ---
    {
        int r = tid >> 1, h = tid & 1;
        unsigned long long best[KNN];
#pragma unroll
        for (int j = 0; j < KNN; j++) best[j] = ~0ULL;
        for (int c2 = 0; c2 < 64; c2++) {
            int col = h + 2*c2;
            float d = Ds[r*PADW + col];
            unsigned long long key =
                ((unsigned long long)__float_as_uint(d) << 32) | (unsigned)(ct*128 + col);
            if (key < best[KNN-1]) {
                best[KNN-1] = key;
#pragma unroll
                for (int j = KNN-1; j > 0; j--)
                    if (best[j] < best[j-1]) {
                        unsigned long long t2 = best[j]; best[j] = best[j-1]; best[j-1] = t2;
                    }
            }
        }
        merge_pair(best);
        if (h == 0) {
            size_t rowg = (size_t)(bb*NPTS + rt*128 + r);
#pragma unroll
            for (int j = 0; j < KNN; j++) g_CAND[(rowg*NT + ct)*KNN + j] = best[j];
        }
    }
    // --- col scan for off-diagonal tiles ---
    if (rt != ct) {
        int c = tid >> 1, h = tid & 1;
        unsigned long long best[KNN];
#pragma unroll
        for (int j = 0; j < KNN; j++) best[j] = ~0ULL;
        for (int r2 = 0; r2 < 64; r2++) {
            int row = h + 2*r2;
            float d = Ds[row*PADW + c];
            unsigned long long key =
                ((unsigned long long)__float_as_uint(d) << 32) | (unsigned)(rt*128 + row);
            if (key < best[KNN-1]) {
                best[KNN-1] = key;
#pragma unroll
                for (int j = KNN-1; j > 0; j--)
                    if (best[j] < best[j-1]) {
                        unsigned long long t2 = best[j]; best[j] = best[j-1]; best[j-1] = t2;
                    }
            }
        }
        merge_pair(best);
        if (h == 0) {
            size_t rowg = (size_t)(bb*NPTS + ct*128 + c);
#pragma unroll
            for (int j = 0; j < KNN; j++) g_CAND[(rowg*NT + rt)*KNN + j] = best[j];
        }
    }
}

// -------- merge 32 sorted 5-lists per row -> NBR, then compute logprobs --------
__global__ void k_merge_lp(int layer, const float* __restrict__ tptr,
                           float* __restrict__ lp_out) {
    int gw   = (blockIdx.x * blockDim.x + threadIdx.x) >> 5;   // row
    int lane = threadIdx.x & 31;
    if (gw >= NN) return;
    int bb = gw >> 12, jj = gw & 4095;
    const unsigned long long* cp = g_CAND + ((size_t)gw*NT + lane)*KNN;
    unsigned long long keys[KNN];
#pragma unroll
    for (int j = 0; j < KNN; j++) keys[j] = cp[j];
    unsigned nbr[KNN];
#pragma unroll
    for (int r = 0; r < KNN; r++) {
        unsigned long long cand = keys[0];
        unsigned long long m = cand;
#pragma unroll
        for (int off = 16; off; off >>= 1) {
            unsigned long long o = __shfl_xor_sync(0xffffffffu, m, off);
            if (o < m) m = o;
        }
        if (m == cand) {   // keys unique (contain index): exactly one winner
#pragma unroll
            for (int j = 0; j < KNN-1; j++) keys[j] = keys[j+1];
            keys[KNN-1] = ~0ULL;
        }
        nbr[r] = (unsigned)(m & 0xffffffffu);
        if (lane == 0) g_NBR[gw*KNN + r] = (int)nbr[r];
    }
    // logprobs for the 5 flat entries of this row (faithful scrambled layout)
    const float* GE = layer ? g_GE2 : g_GE1;
    float tv = tptr[0]; tv = fminf(fmaxf(tv, -5.f), 5.f);
    float t = expf(tv);
#pragma unroll
    for (int r = 0; r < KNN; r++) {
        int a  = (int)nbr[r];
        int mf = r*NPTS + jj;              // k-major flat index
        int p  = mf / KNN, q = mf - p*KNN; // node-major logprob slot
        const float* ga = GE + (bb*NPTS + a)*DIM;
        const float* gp = GE + (bb*NPTS + p)*DIM;
        float s = 0.f;
#pragma unroll
        for (int u = 0; u < 2; u++) {
            float d = ga[lane + 32*u] - gp[lane + 32*u];
            s = fmaf(d, d, s);
        }
#pragma unroll
        for (int off = 16; off; off >>= 1) s += __shfl_xor_sync(0xffffffffu, s, off);
        if (lane == 0)
            lp_out[((bb*NPTS + p)*KNN + q)*2 + layer] = -s * t;
    }
}

// ---------------- EdgeConv node pre-GEMMs: A=X@(Wtop-Wbot), B=X@Wbot, ACC=0 ---
__global__ void k_AB(int layer, const float* __restrict__ W) {
    int v = blockIdx.x, o = threadIdx.x;   // 64 threads
    const float* X = layer ? g_ACC1 : g_X1;
    float* ACC = layer ? g_ACC2 : g_ACC1;
    __shared__ float xr[64];
    xr[o] = X[v*64 + o];
    __syncthreads();
    float a = 0.f, b = 0.f;
#pragma unroll
    for (int d = 0; d < 64; d++) {
        float w1 = W[d*64 + o], w2 = W[(64 + d)*64 + o];
        float xd = xr[d];
        a = fmaf(xd, w1 - w2, a);
        b = fmaf(xd, w2, b);
    }
    g_A[v*64 + o] = a;
    g_B[v*64 + o] = b;
    ACC[v*64 + o] = 0.f;
}

// ---------------- EdgeConv scatter-max ----------------
__global__ void k_scatter(int layer, const float* __restrict__ bias) {
    int tid = blockIdx.x * blockDim.x + threadIdx.x;   // (edge, half)
    if (tid >= NEDGE * 2) return;
    int s  = tid >> 1, h = tid & 1;
    int p0 = s >> 2, bb = (s >> 1) & 1, c = s & 1;
    int src, dst;
    if (c == 0) src = g_NBR[(bb*NPTS + (p0 & 4095))*KNN + (p0 >> 12)] + bb*NPTS;
    else        src = p0 / KNN + bb*NPTS;
    int p1 = p0 + NKM/2;
    if (c == 0) dst = g_NBR[(bb*NPTS + (p1 & 4095))*KNN + (p1 >> 12)] + bb*NPTS;
    else        dst = p1 / KNN + bb*NPTS;

    float* ACC = layer ? g_ACC2 : g_ACC1;
    const float4* Ad = (const float4*)(g_A + dst*64 + h*32);
    const float4* Bv = (const float4*)(g_B + src*64 + h*32);
    const float4* Bi = (const float4*)(bias + h*32);
    int* out = (int*)(ACC + dst*64 + h*32);
#pragma unroll
    for (int o = 0; o < 8; o++) {
        float4 av = Ad[o], bv = Bv[o], bi = Bi[o];
        float m0 = av.x + bv.x + bi.x;
        float m1 = av.y + bv.y + bi.y;
        float m2 = av.z + bv.z + bi.z;
        float m3 = av.w + bv.w + bi.w;
        if (m0 > 0.f) atomicMax(&out[o*4 + 0], __float_as_int(m0));
        if (m1 > 0.f) atomicMax(&out[o*4 + 1], __float_as_int(m1));
        if (m2 > 0.f) atomicMax(&out[o*4 + 2], __float_as_int(m2));
        if (m3 > 0.f) atomicMax(&out[o*4 + 3], __float_as_int(m3));
    }
}

// ---------------- final MLP 64 -> 32 -> 8 ----------------
__global__ void k_fc(const float* __restrict__ W1, const float* __restrict__ b1,
                     const float* __restrict__ W2, const float* __restrict__ b2,
                     float* __restrict__ out) {
    int v = blockIdx.x, o = threadIdx.x;   // 32 threads
    __shared__ float xr[64];
    __shared__ float hr[32];
    xr[o]      = g_ACC2[v*64 + o];
    xr[32 + o] = g_ACC2[v*64 + 32 + o];
    __syncthreads();
    float hh = b1[o];
#pragma unroll
    for (int d = 0; d < 64; d++) hh = fmaf(xr[d], W1[d*32 + o], hh);
    hh = hh > 0.f ? hh : 0.1f * hh;
    hr[o] = hh;
    __syncthreads();
    if (o < 8) {
        float acc = b2[o];
#pragma unroll
        for (int d = 0; d < 32; d++) acc = fmaf(hr[d], W2[d*8 + o], acc);
        out[v*8 + o] = acc;
    }
}

// ======================= launcher =======================
extern "C" void kernel_launch(void* const* d_in, const int* in_sizes, int n_in,
                              void* d_out, int out_size) {
    const float* x     = (const float*)d_in[0];
    const float* W_pre = (const float*)d_in[1];
    const float* b_pre = (const float*)d_in[2];
    const float* W_d1  = (const float*)d_in[3];
    const float* b_d1  = (const float*)d_in[4];
    const float* t1    = (const float*)d_in[5];
    const float* W_c1  = (const float*)d_in[6];
    const float* b_c1  = (const float*)d_in[7];
    const float* W_d2  = (const float*)d_in[8];
    const float* b_d2  = (const float*)d_in[9];
    const float* t2    = (const float*)d_in[10];
    const float* W_c2  = (const float*)d_in[11];
    const float* b_c2  = (const float*)d_in[12];
    const float* W_f1  = (const float*)d_in[13];
    const float* b_f1  = (const float*)d_in[14];
    const float* W_f2  = (const float*)d_in[15];
    const float* b_f2  = (const float*)d_in[16];

    float* out = (float*)d_out;                 // [2,4096,8]
    float* lp  = out + NN * 8;                  // [2,4096,5,2]

    cudaFuncSetAttribute(k_fused, cudaFuncAttributeMaxDynamicSharedMemorySize, SMEMF);

    // layer 1
    k_prefc<<<NN, 64>>>(x, W_pre, b_pre, W_d1, b_d1);
    k_fused<<<NITEMS, 256, SMEMF>>>(0);
    k_merge_lp<<<NN/8, 256>>>(0, t1, lp);
    k_AB<<<NN, 64>>>(0, W_c1);
    k_scatter<<<(NEDGE*2 + 255)/256, 256>>>(0, b_c1);

    // layer 2
    k_embed2<<<NN, 64>>>(W_d2, b_d2);
    k_fused<<<NITEMS, 256, SMEMF>>>(1);
    k_merge_lp<<<NN/8, 256>>>(1, t2, lp);
    k_AB<<<NN, 64>>>(1, W_c2);
    k_scatter<<<(NEDGE*2 + 255)/256, 256>>>(1, b_c2);

    // head
    k_fc<<<NN, 32>>>(W_f1, b_f1, W_f2, b_f2, out);
}

// round 4
// speedup vs baseline: 1.6804x; 1.0425x over previous
#include <cuda_runtime.h>
#include <math.h>

#define NPTS 4096
#define NB   2
#define NN   (NPTS*NB)      // 8192 nodes
#define DIM  64
#define KNN  5
#define NKM  (NPTS*KNN)     // 20480 flat edges per batch
#define NEDGE (NKM*NB)      // 40960 edges total
#define NT   32             // 4096/128 tiles per side
#define NITEMS_B (NT*(NT+1)/2)   // 528 upper-tri items per batch
#define NITEMS   (NB*NITEMS_B)   // 1056

#define PADW 132
#define SMEMF ((32*128*2 + 128*PADW)*4)   // 100352 bytes -> 2 blocks/SM
#define SMEMAB (64*128*2*4)               // 65536 bytes for k_AB

typedef unsigned long long ull;

// -------- scratch (static device globals; no runtime allocation) ----------
__device__ float g_X1 [NN*DIM];
__device__ float g_GE1[NN*DIM];
__device__ float g_GE2[NN*DIM];
__device__ float g_SQ [NN];
__device__ ull   g_CAND[(size_t)NN*NT*KNN];   // 10.5 MB candidates
__device__ int   g_NBR[NN*KNN];
__device__ float g_A  [NN*DIM];
__device__ float g_B  [NN*DIM];
__device__ float g_ACC1[NN*DIM];
__device__ float g_ACC2[NN*DIM];

__device__ __forceinline__ int swz4(int c)  { return c ^ (c >> 3); }
__device__ __forceinline__ int swzb(int c)  { return swz4(c >> 2)*4 + (c & 3); }

// packed fp32x2 FMA: d = a*b + d (elementwise on (lo,hi))
__device__ __forceinline__ void ffma2(ull &d, ull a, ull b) {
    asm("fma.rn.f32x2 %0, %1, %2, %0;" : "+l"(d) : "l"(a), "l"(b));
}
__device__ __forceinline__ ull dup2(float x) {
    ull r;
    asm("mov.b64 %0, {%1, %1};" : "=l"(r) : "f"(x));
    return r;
}
union P2 { ull q; float2 f; };

// ---------------- pre_fc + embed1 + sq ----------------
__global__ void k_prefc(const float* __restrict__ x,
                        const float* __restrict__ Wp, const float* __restrict__ bp,
                        const float* __restrict__ Wd, const float* __restrict__ bd) {
    int v = blockIdx.x;
    int o = threadIdx.x;           // 64 threads
    __shared__ float xr[32];
    __shared__ float x1r[64];
    __shared__ float red[64];
    if (o < 32) xr[o] = x[v*32 + o];
    __syncthreads();
    float acc = bp[o];
#pragma unroll
    for (int d = 0; d < 32; d++) acc = fmaf(xr[d], Wp[d*64 + o], acc);
    acc = acc > 0.f ? acc : 0.1f * acc;          // LeakyReLU(0.1)
    g_X1[v*64 + o] = acc;
    x1r[o] = acc;
    __syncthreads();
    float ge = bd[o];
#pragma unroll
    for (int d = 0; d < 64; d++) ge = fmaf(x1r[d], Wd[d*64 + o], ge);
    g_GE1[v*64 + o] = ge;
    red[o] = ge * ge;
    __syncthreads();
    for (int s = 32; s > 0; s >>= 1) { if (o < s) red[o] += red[o + s]; __syncthreads(); }
    if (o == 0) g_SQ[v] = red[0];
}

// ---------------- embed2 (concat(GE1, X2) @ W_d2) + sq ----------------
__global__ void k_embed2(const float* __restrict__ Wd, const float* __restrict__ bd) {
    int v = blockIdx.x, o = threadIdx.x;   // 64 threads
    __shared__ float gr[128];
    __shared__ float red[64];
    gr[o]      = g_GE1 [v*64 + o];
    gr[64 + o] = g_ACC1[v*64 + o];
    __syncthreads();
    float ge = bd[o];
#pragma unroll
    for (int d = 0; d < 128; d++) ge = fmaf(gr[d], Wd[d*64 + o], ge);
    g_GE2[v*64 + o] = ge;
    red[o] = ge * ge;
    __syncthreads();
    for (int s = 32; s > 0; s >>= 1) { if (o < s) red[o] += red[o + s]; __syncthreads(); }
    if (o == 0) g_SQ[v] = red[0];
}

// ---- merge two sorted 5-lists held by adjacent lanes (xor 1); result in best ----
__device__ __forceinline__ void merge_pair(ull best[KNN]) {
    ull other[KNN];
#pragma unroll
    for (int j = 0; j < KNN; j++) other[j] = __shfl_xor_sync(0xffffffffu, best[j], 1);
#pragma unroll
    for (int j = 0; j < KNN; j++) {
        ull key = other[j];
        if (key < best[KNN-1]) {
            best[KNN-1] = key;
#pragma unroll
            for (int u = KNN-1; u > 0; u--)
                if (best[u] < best[u-1]) {
                    ull t2 = best[u]; best[u] = best[u-1]; best[u-1] = t2;
                }
        }
    }
}

// ============ fused symmetric distance GEMM + per-tile top-5 extraction ============
__global__ void __launch_bounds__(256, 2)
k_fused(int layer) {
    extern __shared__ float sm[];
    float* As = sm;                 // [32 k][128 rows] chunk-swizzled
    float* Bs = sm + 32*128;
    float* Ds = sm + 64*128;        // [128][PADW]

    const float* GE = layer ? g_GE2 : g_GE1;
    int item = blockIdx.x;
    int bb  = item / NITEMS_B;
    int tri = item - bb*NITEMS_B;
    int rt = 0;
    while (tri >= NT - rt) { tri -= NT - rt; rt++; }
    int ct = rt + tri;

    const float* G  = GE + bb*NPTS*DIM;
    const float* sq = g_SQ + bb*NPTS;
    int tid = threadIdx.x;
    int ty = tid >> 4, tx = tid & 15;
    int r32 = tid & 31;             // row subgroup for loading
    int kq2 = tid >> 5;             // 0..7: float4-of-k index within chunk
    const float4* G4 = (const float4*)G;
    const float4* As4 = (const float4*)As;
    const ulonglong2* Bs8 = (const ulonglong2*)Bs;
    int pa0 = swz4(2*ty), pa1 = swz4(2*ty+1);
    int pb0 = swz4(2*tx), pb1 = swz4(2*tx+1);

    ull acc[8][4];
#pragma unroll
    for (int u = 0; u < 8; u++)
#pragma unroll
        for (int v = 0; v < 4; v++) acc[u][v] = 0ULL;

#pragma unroll
    for (int chunk = 0; chunk < 2; chunk++) {
        if (chunk) __syncthreads();          // protect smem reuse
#pragma unroll
        for (int it = 0; it < 4; it++) {
            int row = it*32 + r32;
            float4 va = G4[(rt*128 + row)*16 + chunk*8 + kq2];
            float4 vb = G4[(ct*128 + row)*16 + chunk*8 + kq2];
            int base = swz4(row >> 2)*4 + (row & 3);
            As[(kq2*4+0)*128 + base] = va.x;
            As[(kq2*4+1)*128 + base] = va.y;
            As[(kq2*4+2)*128 + base] = va.z;
            As[(kq2*4+3)*128 + base] = va.w;
            Bs[(kq2*4+0)*128 + base] = vb.x;
            Bs[(kq2*4+1)*128 + base] = vb.y;
            Bs[(kq2*4+2)*128 + base] = vb.z;
            Bs[(kq2*4+3)*128 + base] = vb.w;
        }
        __syncthreads();
#pragma unroll 8
        for (int k = 0; k < 32; k++) {
            float4 a0 = As4[k*32 + pa0];
            float4 a1 = As4[k*32 + pa1];
            ulonglong2 vb0 = Bs8[k*32 + pb0];
            ulonglong2 vb1 = Bs8[k*32 + pb1];
            ull ad[8];
            ad[0] = dup2(a0.x); ad[1] = dup2(a0.y); ad[2] = dup2(a0.z); ad[3] = dup2(a0.w);
            ad[4] = dup2(a1.x); ad[5] = dup2(a1.y); ad[6] = dup2(a1.z); ad[7] = dup2(a1.w);
            ull bp[4] = {vb0.x, vb0.y, vb1.x, vb1.y};
#pragma unroll
            for (int u = 0; u < 8; u++)
#pragma unroll
                for (int v = 0; v < 4; v++)
                    ffma2(acc[u][v], ad[u], bp[v]);
        }
    }

    // --- distances to smem (selection is monotone in t; omit it) ---
    float sqr[8], sqc[8];
#pragma unroll
    for (int u = 0; u < 8; u++) sqr[u] = sq[rt*128 + ty*8 + u];
#pragma unroll
    for (int v = 0; v < 8; v++) sqc[v] = sq[ct*128 + tx*8 + v];
#pragma unroll
    for (int u = 0; u < 8; u++) {
        int r = ty*8 + u;
        float dd[8];
#pragma unroll
        for (int vp = 0; vp < 4; vp++) {
            P2 w; w.q = acc[u][vp];
            dd[2*vp]   = fmaxf(sqr[u] + sqc[2*vp]   - 2.f*w.f.x, 0.f);
            dd[2*vp+1] = fmaxf(sqr[u] + sqc[2*vp+1] - 2.f*w.f.y, 0.f);
        }
        float4 d0 = {dd[0], dd[1], dd[2], dd[3]};
        float4 d1 = {dd[4], dd[5], dd[6], dd[7]};
        *(float4*)(Ds + r*PADW + tx*8)     = d0;
        *(float4*)(Ds + r*PADW + tx*8 + 4) = d1;
    }
    __syncthreads();

    // --- row scan: 2 threads/row, interleaved columns, shfl-pair merge ---
    {
        int r = tid >> 1, h = tid & 1;
        ull best[KNN];
#pragma unroll
        for (int j = 0; j < KNN; j++) best[j] = ~0ULL;
        for (int c2 = 0; c2 < 64; c2++) {
            int col = h + 2*c2;
            float d = Ds[r*PADW + col];
            ull key = ((ull)__float_as_uint(d) << 32) | (unsigned)(ct*128 + col);
            if (key < best[KNN-1]) {
                best[KNN-1] = key;
#pragma unroll
                for (int j = KNN-1; j > 0; j--)
                    if (best[j] < best[j-1]) {
                        ull t2 = best[j]; best[j] = best[j-1]; best[j-1] = t2;
                    }
            }
        }
        merge_pair(best);
        if (h == 0) {
            size_t rowg = (size_t)(bb*NPTS + rt*128 + r);
#pragma unroll
            for (int j = 0; j < KNN; j++) g_CAND[(rowg*NT + ct)*KNN + j] = best[j];
        }
    }
    // --- col scan for off-diagonal tiles ---
    if (rt != ct) {
        int c = tid >> 1, h = tid & 1;
        ull best[KNN];
#pragma unroll
        for (int j = 0; j < KNN; j++) best[j] = ~0ULL;
        for (int r2 = 0; r2 < 64; r2++) {
            int row = h + 2*r2;
            float d = Ds[row*PADW + c];
            ull key = ((ull)__float_as_uint(d) << 32) | (unsigned)(rt*128 + row);
            if (key < best[KNN-1]) {
                best[KNN-1] = key;
#pragma unroll
                for (int j = KNN-1; j > 0; j--)
                    if (best[j] < best[j-1]) {
                        ull t2 = best[j]; best[j] = best[j-1]; best[j-1] = t2;
                    }
            }
        }
        merge_pair(best);
        if (h == 0) {
            size_t rowg = (size_t)(bb*NPTS + ct*128 + c);
#pragma unroll
            for (int j = 0; j < KNN; j++) g_CAND[(rowg*NT + rt)*KNN + j] = best[j];
        }
    }
}

// -------- merge 32 sorted 5-lists per row -> NBR, then compute logprobs --------
__global__ void k_merge_lp(int layer, const float* __restrict__ tptr,
                           float* __restrict__ lp_out) {
    int gw   = (blockIdx.x * blockDim.x + threadIdx.x) >> 5;   // row
    int lane = threadIdx.x & 31;
    if (gw >= NN) return;
    int bb = gw >> 12, jj = gw & 4095;
    const ull* cp = g_CAND + ((size_t)gw*NT + lane)*KNN;
    ull keys[KNN];
#pragma unroll
    for (int j = 0; j < KNN; j++) keys[j] = cp[j];
    unsigned nbr[KNN];
#pragma unroll
    for (int r = 0; r < KNN; r++) {
        ull cand = keys[0];
        ull m = cand;
#pragma unroll
        for (int off = 16; off; off >>= 1) {
            ull o = __shfl_xor_sync(0xffffffffu, m, off);
            if (o < m) m = o;
        }
        if (m == cand) {   // keys unique (contain index): exactly one winner
#pragma unroll
            for (int j = 0; j < KNN-1; j++) keys[j] = keys[j+1];
            keys[KNN-1] = ~0ULL;
        }
        nbr[r] = (unsigned)(m & 0xffffffffu);
        if (lane == 0) g_NBR[gw*KNN + r] = (int)nbr[r];
    }
    // logprobs for the 5 flat entries of this row (faithful scrambled layout)
    const float* GE = layer ? g_GE2 : g_GE1;
    float tv = tptr[0]; tv = fminf(fmaxf(tv, -5.f), 5.f);
    float t = expf(tv);
#pragma unroll
    for (int r = 0; r < KNN; r++) {
        int a  = (int)nbr[r];
        int mf = r*NPTS + jj;              // k-major flat index
        int p  = mf / KNN, q = mf - p*KNN; // node-major logprob slot
        const float* ga = GE + (bb*NPTS + a)*DIM;
        const float* gp = GE + (bb*NPTS + p)*DIM;
        float s = 0.f;
#pragma unroll
        for (int u = 0; u < 2; u++) {
            float d = ga[lane + 32*u] - gp[lane + 32*u];
            s = fmaf(d, d, s);
        }
#pragma unroll
        for (int off = 16; off; off >>= 1) s += __shfl_xor_sync(0xffffffffu, s, off);
        if (lane == 0)
            lp_out[((bb*NPTS + p)*KNN + q)*2 + layer] = -s * t;
    }
}

// ------- EdgeConv node pre-GEMM, tiled: [128 nodes] x [A|B out 128] x [64 k] -------
// A = X @ (Wtop - Wbot), B = X @ Wbot; also zero ACC.
__global__ void __launch_bounds__(256)
k_AB(int layer, const float* __restrict__ W) {
    extern __shared__ float sm[];
    float* Xs = sm;            // [64 k][128 nodes] swizzled
    float* Ws = sm + 64*128;   // [64 k][128 cols]  swizzled
    const float* X = layer ? g_ACC1 : g_X1;
    float* ACC = layer ? g_ACC2 : g_ACC1;
    int tid = threadIdx.x;
    int nt = blockIdx.x;       // node tile (128 nodes)

    // load X tile (k-major, swizzled): 128 rows x 16 float4
    const float4* X4 = (const float4*)X;
    int r16 = tid & 15, kq = tid >> 4;   // kq 0..15
#pragma unroll
    for (int it = 0; it < 8; it++) {
        int row = it*16 + r16;
        float4 v = X4[((size_t)nt*128 + row)*16 + kq];
        int base = swzb(row);
        Xs[(kq*4+0)*128 + base] = v.x;
        Xs[(kq*4+1)*128 + base] = v.y;
        Xs[(kq*4+2)*128 + base] = v.z;
        Xs[(kq*4+3)*128 + base] = v.w;
    }
    // build Ws: col<64 -> Wtop-Wbot ; col>=64 -> Wbot
    for (int i = 0; i < 32; i++) {
        int idx = tid + i*256;           // 8192 entries
        int k = idx >> 7, col = idx & 127;
        float val = (col < 64) ? (W[k*64 + col] - W[(64+k)*64 + col])
                               : W[(64+k)*64 + (col-64)];
        Ws[k*128 + swzb(col)] = val;
    }
    __syncthreads();

    int ty = tid >> 4, tx = tid & 15;
    const float4* As4 = (const float4*)Xs;
    const ulonglong2* Bs8 = (const ulonglong2*)Ws;
    int pa0 = swz4(2*ty), pa1 = swz4(2*ty+1);
    int pb0 = swz4(2*tx), pb1 = swz4(2*tx+1);
    ull acc[8][4];
#pragma unroll
    for (int u = 0; u < 8; u++)
#pragma unroll
        for (int v = 0; v < 4; v++) acc[u][v] = 0ULL;
#pragma unroll 8
    for (int k = 0; k < 64; k++) {
        float4 a0 = As4[k*32 + pa0];
        float4 a1 = As4[k*32 + pa1];
        ulonglong2 vb0 = Bs8[k*32 + pb0];
        ulonglong2 vb1 = Bs8[k*32 + pb1];
        ull ad[8];
        ad[0] = dup2(a0.x); ad[1] = dup2(a0.y); ad[2] = dup2(a0.z); ad[3] = dup2(a0.w);
        ad[4] = dup2(a1.x); ad[5] = dup2(a1.y); ad[6] = dup2(a1.z); ad[7] = dup2(a1.w);
        ull bp[4] = {vb0.x, vb0.y, vb1.x, vb1.y};
#pragma unroll
        for (int u = 0; u < 8; u++)
#pragma unroll
            for (int v = 0; v < 4; v++)
                ffma2(acc[u][v], ad[u], bp[v]);
    }

    // epilogue: tx<8 -> A-half (and zero ACC), tx>=8 -> B-half
#pragma unroll
    for (int u = 0; u < 8; u++) {
        int node = nt*128 + ty*8 + u;
#pragma unroll
        for (int vp = 0; vp < 4; vp++) {
            P2 w; w.q = acc[u][vp];
            int c = tx*8 + 2*vp;
            if (c < 64) {
                *(float2*)(g_A + (size_t)node*64 + c) = w.f;
                float2 z = {0.f, 0.f};
                *(float2*)(ACC + (size_t)node*64 + c) = z;
            } else {
                *(float2*)(g_B + (size_t)node*64 + (c-64)) = w.f;
            }
        }
    }
}

// ---------------- EdgeConv scatter-max ----------------
__global__ void k_scatter(int layer, const float* __restrict__ bias) {
    int tid = blockIdx.x * blockDim.x + threadIdx.x;   // (edge, half)
    if (tid >= NEDGE * 2) return;
    int s  = tid >> 1, h = tid & 1;
    int p0 = s >> 2, bb = (s >> 1) & 1, c = s & 1;
    int src, dst;
    if (c == 0) src = g_NBR[(bb*NPTS + (p0 & 4095))*KNN + (p0 >> 12)] + bb*NPTS;
    else        src = p0 / KNN + bb*NPTS;
    int p1 = p0 + NKM/2;
    if (c == 0) dst = g_NBR[(bb*NPTS + (p1 & 4095))*KNN + (p1 >> 12)] + bb*NPTS;
    else        dst = p1 / KNN + bb*NPTS;

    float* ACC = layer ? g_ACC2 : g_ACC1;
    const float4* Ad = (const float4*)(g_A + dst*64 + h*32);
    const float4* Bv = (const float4*)(g_B + src*64 + h*32);
    const float4* Bi = (const float4*)(bias + h*32);
    int* out = (int*)(ACC + dst*64 + h*32);
#pragma unroll
    for (int o = 0; o < 8; o++) {
        float4 av = Ad[o], bv = Bv[o], bi = Bi[o];
        float m0 = av.x + bv.x + bi.x;
        float m1 = av.y + bv.y + bi.y;
        float m2 = av.z + bv.z + bi.z;
        float m3 = av.w + bv.w + bi.w;
        if (m0 > 0.f) atomicMax(&out[o*4 + 0], __float_as_int(m0));
        if (m1 > 0.f) atomicMax(&out[o*4 + 1], __float_as_int(m1));
        if (m2 > 0.f) atomicMax(&out[o*4 + 2], __float_as_int(m2));
        if (m3 > 0.f) atomicMax(&out[o*4 + 3], __float_as_int(m3));
    }
}

// ---------------- final MLP 64 -> 32 -> 8 ----------------
__global__ void k_fc(const float* __restrict__ W1, const float* __restrict__ b1,
                     const float* __restrict__ W2, const float* __restrict__ b2,
                     float* __restrict__ out) {
    int v = blockIdx.x, o = threadIdx.x;   // 32 threads
    __shared__ float xr[64];
    __shared__ float hr[32];
    xr[o]      = g_ACC2[v*64 + o];
    xr[32 + o] = g_ACC2[v*64 + 32 + o];
    __syncthreads();
    float hh = b1[o];
#pragma unroll
    for (int d = 0; d < 64; d++) hh = fmaf(xr[d], W1[d*32 + o], hh);
    hh = hh > 0.f ? hh : 0.1f * hh;
    hr[o] = hh;
    __syncthreads();
    if (o < 8) {
        float acc = b2[o];
#pragma unroll
        for (int d = 0; d < 32; d++) acc = fmaf(hr[d], W2[d*8 + o], acc);
        out[v*8 + o] = acc;
    }
}

// ======================= launcher =======================
extern "C" void kernel_launch(void* const* d_in, const int* in_sizes, int n_in,
                              void* d_out, int out_size) {
    const float* x     = (const float*)d_in[0];
    const float* W_pre = (const float*)d_in[1];
    const float* b_pre = (const float*)d_in[2];
    const float* W_d1  = (const float*)d_in[3];
    const float* b_d1  = (const float*)d_in[4];
    const float* t1    = (const float*)d_in[5];
    const float* W_c1  = (const float*)d_in[6];
    const float* b_c1  = (const float*)d_in[7];
    const float* W_d2  = (const float*)d_in[8];
    const float* b_d2  = (const float*)d_in[9];
    const float* t2    = (const float*)d_in[10];
    const float* W_c2  = (const float*)d_in[11];
    const float* b_c2  = (const float*)d_in[12];
    const float* W_f1  = (const float*)d_in[13];
    const float* b_f1  = (const float*)d_in[14];
    const float* W_f2  = (const float*)d_in[15];
    const float* b_f2  = (const float*)d_in[16];

    float* out = (float*)d_out;                 // [2,4096,8]
    float* lp  = out + NN * 8;                  // [2,4096,5,2]

    cudaFuncSetAttribute(k_fused, cudaFuncAttributeMaxDynamicSharedMemorySize, SMEMF);
    cudaFuncSetAttribute(k_AB,    cudaFuncAttributeMaxDynamicSharedMemorySize, SMEMAB);

    // layer 1
    k_prefc<<<NN, 64>>>(x, W_pre, b_pre, W_d1, b_d1);
    k_fused<<<NITEMS, 256, SMEMF>>>(0);
    k_merge_lp<<<NN/8, 256>>>(0, t1, lp);
    k_AB<<<NN/128, 256, SMEMAB>>>(0, W_c1);
    k_scatter<<<(NEDGE*2 + 255)/256, 256>>>(0, b_c1);

    // layer 2
    k_embed2<<<NN, 64>>>(W_d2, b_d2);
    k_fused<<<NITEMS, 256, SMEMF>>>(1);
    k_merge_lp<<<NN/8, 256>>>(1, t2, lp);
    k_AB<<<NN/128, 256, SMEMAB>>>(1, W_c2);
    k_scatter<<<(NEDGE*2 + 255)/256, 256>>>(1, b_c2);

    // head
    k_fc<<<NN, 32>>>(W_f1, b_f1, W_f2, b_f2, out);
}